// round 9
// baseline (speedup 1.0000x reference)
#include <cuda_runtime.h>
#include <math.h>

#define BB 8
#define SS 4
#define NN 8192
#define MM 50
#define BSN (BB*SS*NN)   // 262144
#define INF_F 3.4e38f
#define GRID_BLKS 148
#define NTHREADS 256
#define GRID_THREADS (GRID_BLKS*NTHREADS)   // 37888
#define NTASK (25*SS*BB)                    // 800

// ---------------- scratch (no allocations allowed) ----------------
__device__ float    g_px[BSN];
__device__ float    g_py[BSN];
__device__ float    g_pz[BSN];
__device__ int      g_assign[BSN];
__device__ unsigned g_flag[BB*SS];
// 0: center_sum, 1: n_pos, 2: sum_pos softplus(-x), 3: sum_neg softplus(x), 4: sum_unmatched
__device__ double   g_acc[5];
__device__ unsigned g_done;
__device__ unsigned g_work;
__device__ unsigned g_barc;   // monotonic ticket counter (never reset; replay-safe)

// grid-wide barrier: monotonic tickets, target = next multiple of GRID_BLKS.
// Correct even when arrivals of consecutive barriers overlap in time, and
// across CUDA-graph replays (counter keeps counting up). Deadlock-free as
// long as all GRID_BLKS blocks are co-resident: 148 blocks <= 148 SMs at
// occupancy >= 1 (64KB smem, 256 threads -> occupancy is >= 2).
__device__ __forceinline__ void grid_barrier() {
    __syncthreads();
    if (threadIdx.x == 0) {
        __threadfence();
        const unsigned t = atomicAdd(&g_barc, 1u);
        const unsigned target = (t / GRID_BLKS + 1u) * GRID_BLKS;
        while (*((volatile unsigned*)&g_barc) < target) __nanosleep(64);
        __threadfence();
    }
    __syncthreads();
}

// lexicographic (val, idx) warp min -> valid on lane 0
__device__ __forceinline__ void warp_min(float& v, int& i) {
    #pragma unroll
    for (int off = 16; off; off >>= 1) {
        float ov = __shfl_down_sync(0xffffffffu, v, off);
        int   oi = __shfl_down_sync(0xffffffffu, i, off);
        if (ov < v || (ov == v && oi < i)) { v = ov; i = oi; }
    }
}

// ---------------- fused persistent kernel: prep | topk | reduce ----------------
__global__ void __launch_bounds__(NTHREADS, 2)
fused_kernel(const float* __restrict__ pb,
             const float* __restrict__ gtb,
             const int*   __restrict__ n_gt,
             const float* __restrict__ scores,
             float* __restrict__ out,
             const float* __restrict__ wc,
             const float* __restrict__ wo,
             const float* __restrict__ wu) {
    extern __shared__ float smem[];
    float* sd0 = smem;            // [8192]
    float* sd1 = smem + NN;       // [8192]
    __shared__ float segv[2][64];
    __shared__ int   segi[2][64];
    __shared__ int   s_task;

    const int tid  = threadIdx.x;
    const int w    = tid >> 5;
    const int lane = tid & 31;
    const int gid  = blockIdx.x * NTHREADS + tid;

    // ================= Phase A: planarize coords + init scratch =================
    // (proven R6 float4 transposition: box j of quad t reads flat floats
    //  F[28t+7j+{0,1,2}] = components of q0..q5)
    for (int t = gid; t < BSN/4; t += GRID_THREADS) {
        const float4* q = (const float4*)pb;
        const size_t base = (size_t)t * 7;
        const float4 q0 = q[base+0], q1 = q[base+1], q2 = q[base+2];
        const float4 q3 = q[base+3], q4 = q[base+4], q5 = q[base+5];
        ((float4*)g_px)[t] = make_float4(q0.x, q1.w, q3.z, q5.y);
        ((float4*)g_py)[t] = make_float4(q0.y, q2.x, q3.w, q5.z);
        ((float4*)g_pz)[t] = make_float4(q0.z, q2.y, q4.x, q5.w);
        ((int4*)g_assign)[t] = make_int4(-1, -1, -1, -1);
    }
    if (gid < BB*SS) g_flag[gid] = 0u;
    if (gid < 5)     g_acc[gid]  = 0.0;
    if (gid == 0)  { g_done = 0u; g_work = 0u; }

    grid_barrier();

    // ================= Phase B: per-(b,s,gt-pair) top-10 selection =================
    for (;;) {
        __syncthreads();                       // protects s_task + smem reuse
        if (tid == 0) s_task = (int)atomicAdd(&g_work, 1u);
        __syncthreads();
        const int task = s_task;
        if (task >= NTASK) break;              // uniform across block

        const int b   = task / 100;
        const int rem = task - b * 100;
        const int s   = rem / 25;
        const int mp  = rem - s * 25;
        const int m0 = mp * 2, m1 = m0 + 1;
        const int ngt = n_gt[b];
        if (m0 >= ngt) continue;
        const bool has_b = (m1 < ngt);

        const float g0x = gtb[(b*MM + m0)*7 + 0];
        const float g0y = gtb[(b*MM + m0)*7 + 1];
        const float g0z = gtb[(b*MM + m0)*7 + 2];
        const int  mL  = has_b ? m1 : m0;
        const float g1x = gtb[(b*MM + mL)*7 + 0];
        const float g1y = gtb[(b*MM + mL)*7 + 1];
        const float g1z = gtb[(b*MM + mL)*7 + 2];

        const int gbase = (b*SS + s) * NN;

        // ---- phase 1: distances + fused 64x128-segment minima ----
        {
            const int base = w * 1024;
            float rv0 = INF_F, rv1 = INF_F;
            int   ri0 = 0,     ri1 = 0;
            #pragma unroll
            for (int i = 0; i < 32; ++i) {
                const int e = base + i*32 + lane;
                const float x = g_px[gbase + e];
                const float y = g_py[gbase + e];
                const float z = g_pz[gbase + e];
                float dx = x - g0x, dy = y - g0y, dz = z - g0z;
                const float d0 = fmaf(dx, dx, fmaf(dy, dy, dz*dz));
                dx = x - g1x; dy = y - g1y; dz = z - g1z;
                const float d1 = fmaf(dx, dx, fmaf(dy, dy, dz*dz));
                sd0[e] = d0;
                sd1[e] = d1;
                if (d0 < rv0) { rv0 = d0; ri0 = e; }
                if (d1 < rv1) { rv1 = d1; ri1 = e; }
                if ((i & 3) == 3) {
                    float tv0 = rv0; int ti0 = ri0;
                    float tv1 = rv1; int ti1 = ri1;
                    warp_min(tv0, ti0);
                    warp_min(tv1, ti1);
                    if (lane == 0) {
                        const int sg = w*8 + (i >> 2);
                        segv[0][sg] = tv0; segi[0][sg] = ti0;
                        segv[1][sg] = tv1; segi[1][sg] = ti1;
                    }
                    rv0 = INF_F; rv1 = INF_F; ri0 = 0; ri1 = 0;
                }
            }
        }
        __syncthreads();

        // ---- phase 2: 10 selection rounds (warp 0 -> m0, warp 1 -> m1) ----
        if (w < 2 && !(w == 1 && !has_b)) {     // guard form: NO returns
            float* sd  = (w == 0) ? sd0 : sd1;
            float* sgv = segv[w];
            int*   sgi = segi[w];

            float topv[10];
            int   topi[10];
            #pragma unroll
            for (int it = 0; it < 10; ++it) {
                float v  = sgv[lane];      int ei  = sgi[lane];
                float v2 = sgv[lane + 32]; int ei2 = sgi[lane + 32];
                if (v2 < v || (v2 == v && ei2 < ei)) { v = v2; ei = ei2; }
                warp_min(v, ei);
                v  = __shfl_sync(0xffffffffu, v,  0);
                ei = __shfl_sync(0xffffffffu, ei, 0);
                topv[it] = v; topi[it] = ei;
                const int sg = ei >> 7;
                if (lane == 0) sd[ei] = INF_F;
                __syncwarp();
                const int rb = sg*128 + lane*4;
                float nv = INF_F; int ni = rb;
                #pragma unroll
                for (int j = 0; j < 4; ++j) {
                    const float t = sd[rb + j];
                    if (t < nv) { nv = t; ni = rb + j; }
                }
                warp_min(nv, ni);
                if (lane == 0) { sgv[sg] = nv; sgi[sg] = ni; }
                __syncwarp();
            }

            if (lane == 0) {
                const int mm = (w == 0) ? m0 : m1;
                bool matched = false;
                #pragma unroll
                for (int j = 0; j < 10; ++j) {
                    if (sqrtf(topv[j]) < 50.0f) {
                        atomicMax(&g_assign[gbase + topi[j]], mm);
                        matched = true;
                    }
                }
                if (!matched) {
                    float pg = 0.f;
                    #pragma unroll
                    for (int j = 0; j < 5; ++j)
                        pg += expf(-sqrtf(topv[j]) * 0.5f) * (1.0f - scores[gbase + topi[j]]);
                    atomicAdd(&g_acc[4], (double)(pg * 0.2f));
                    atomicOr(&g_flag[b*SS + s], 1u);
                }
            }
        }
    }

    grid_barrier();

    // ================= Phase C: fused reduction + final combine =================
    {
        double c_sum = 0.0, sp1 = 0.0, sp2 = 0.0, np = 0.0;

        for (int i = gid; i < BSN; i += GRID_THREADS) {
            const int a = g_assign[i];
            const float x = scores[i];
            const float l1p = log1pf(expf(-fabsf(x)));   // shared tail of softplus(+-x)
            if (a >= 0) {
                np  += 1.0;
                sp1 += (double)(fmaxf(-x, 0.f) + l1p);    // softplus(-x)
                const int bb = i >> 15;                   // / (S*N)
                const float* g = gtb + (size_t)(bb*MM + a) * 7;
                float dd, ad;
                dd = g_px[i] - g[0]; ad = fabsf(dd);
                c_sum += (double)((ad < 1.f) ? 0.5f*ad*ad : ad - 0.5f);
                dd = g_py[i] - g[1]; ad = fabsf(dd);
                c_sum += (double)((ad < 1.f) ? 0.5f*ad*ad : ad - 0.5f);
                dd = g_pz[i] - g[2]; ad = fabsf(dd);
                c_sum += (double)((ad < 1.f) ? 0.5f*ad*ad : ad - 0.5f);
            } else {
                sp2 += (double)(fmaxf(x, 0.f) + l1p);     // softplus(x)
            }
        }

        #pragma unroll
        for (int off = 16; off; off >>= 1) {
            c_sum += __shfl_down_sync(0xffffffffu, c_sum, off);
            sp1   += __shfl_down_sync(0xffffffffu, sp1,   off);
            sp2   += __shfl_down_sync(0xffffffffu, sp2,   off);
            np    += __shfl_down_sync(0xffffffffu, np,    off);
        }
        __shared__ double sm[4][8];
        if (lane == 0) { sm[0][w]=c_sum; sm[1][w]=sp1; sm[2][w]=sp2; sm[3][w]=np; }
        __syncthreads();
        if (tid == 0) {
            #pragma unroll
            for (int k = 1; k < 8; ++k) { c_sum+=sm[0][k]; sp1+=sm[1][k]; sp2+=sm[2][k]; np+=sm[3][k]; }
            atomicAdd(&g_acc[0], c_sum);
            atomicAdd(&g_acc[1], np);
            atomicAdd(&g_acc[2], sp1);
            atomicAdd(&g_acc[3], sp2);
            __threadfence();
            const unsigned t = atomicAdd(&g_done, 1u);
            if (t == GRID_BLKS - 1) {
                const double npos = g_acc[1];
                const double loss_center = g_acc[0] / fmax(npos * 3.0, 1.0);
                const double nneg = (double)BSN - npos;
                const double pw = fmin(10.0, nneg / fmax(npos, 1.0));
                const double loss_obj = (pw * g_acc[2] + g_acc[3]) / (double)BSN;
                int ne = 0;
                #pragma unroll
                for (int k = 0; k < BB*SS; ++k) ne += (g_flag[k] ? 1 : 0);
                const double loss_unm = g_acc[4] / fmax((double)ne, 1.0);
                out[0] = (float)(loss_center * (double)wc[0] +
                                 loss_obj    * (double)wo[0] +
                                 loss_unm    * (double)wu[0]);
            }
        }
    }
}

// ---------------- launch ----------------
extern "C" void kernel_launch(void* const* d_in, const int* in_sizes, int n_in,
                              void* d_out, int out_size) {
    const float* pb     = (const float*)d_in[0];   // pred_boxes  [8,4,8192,7]
    const float* scores = (const float*)d_in[2];   // pred_scores [8,4,8192]
    const float* gtb    = (const float*)d_in[3];   // gt_boxes    [8,50,7]
    const int*   n_gt   = (const int*)d_in[5];     // [8]
    const float* wc     = (const float*)d_in[6];
    const float* wo     = (const float*)d_in[7];
    const float* wu     = (const float*)d_in[8];
    float* out = (float*)d_out;

    const int smem_bytes = 2 * NN * sizeof(float);   // 64 KB dynamic
    static bool attr_set = false;
    if (!attr_set) {
        cudaFuncSetAttribute(fused_kernel,
                             cudaFuncAttributeMaxDynamicSharedMemorySize,
                             smem_bytes);
        attr_set = true;
    }

    fused_kernel<<<GRID_BLKS, NTHREADS, smem_bytes>>>(
        pb, gtb, n_gt, scores, out, wc, wo, wu);
}

// round 10
// speedup vs baseline: 1.5017x; 1.5017x over previous
#include <cuda_runtime.h>
#include <math.h>

#define BB 8
#define SS 4
#define NN 8192
#define MM 50
#define BSN (BB*SS*NN)   // 262144
#define INF_F 3.4e38f

// ---------------- scratch (no allocations allowed) ----------------
__device__ float    g_px[BSN];
__device__ float    g_py[BSN];
__device__ float    g_pz[BSN];
__device__ int      g_assign[BSN];
__device__ unsigned g_flag[BB*SS];
// 0: center_sum, 1: n_pos, 2: sum_pos softplus(-x), 3: sum_neg softplus(x), 4: sum_unmatched
__device__ double   g_acc[5];
__device__ unsigned g_done;

// ---------------- prep: planarize coords (float4) + init scratch ----------------
// 4 boxes per thread: 6 coalesced float4 reads cover the 3 needed coords of
// all 4 boxes (flat floats F[28t..28t+27]; box j coords = F[28t+7j+{0,1,2}]).
__global__ void prep_kernel(const float* __restrict__ pb) {
    const int t = blockIdx.x * blockDim.x + threadIdx.x;   // 65536 threads
    const float4* q = (const float4*)pb;
    const size_t base = (size_t)t * 7;                     // float4 units
    const float4 q0 = q[base+0], q1 = q[base+1], q2 = q[base+2];
    const float4 q3 = q[base+3], q4 = q[base+4], q5 = q[base+5];
    float4 X = make_float4(q0.x, q1.w, q3.z, q5.y);        // F0,F7,F14,F21
    float4 Y = make_float4(q0.y, q2.x, q3.w, q5.z);        // F1,F8,F15,F22
    float4 Z = make_float4(q0.z, q2.y, q4.x, q5.w);        // F2,F9,F16,F23
    ((float4*)g_px)[t] = X;
    ((float4*)g_py)[t] = Y;
    ((float4*)g_pz)[t] = Z;
    ((int4*)g_assign)[t] = make_int4(-1, -1, -1, -1);
    if (t < BB*SS) g_flag[t] = 0u;
    if (t < 5)     g_acc[t]  = 0.0;
    if (t == 0)    g_done    = 0u;
}

// lexicographic (val, idx) warp min -> valid on lane 0
__device__ __forceinline__ void warp_min(float& v, int& i) {
    #pragma unroll
    for (int off = 16; off; off >>= 1) {
        float ov = __shfl_down_sync(0xffffffffu, v, off);
        int   oi = __shfl_down_sync(0xffffffffu, i, off);
        if (ov < v || (ov == v && oi < i)) { v = ov; i = oi; }
    }
}

// ---------------- per-(b,s,gt-pair) top-10 selection ----------------
// One 256-thread block per (b, s, gt-pair). Phase 1: all 8 warps compute
// squared distances for both gts into 2x32KB smem via float4 loads/stores;
// each of the 8 steps covers exactly one 128-elem segment per warp (same
// element sets as the proven scalar version -> identical segment minima).
// Phase 2 (UNCHANGED, proven): warp 0 selects for m0, warp 1 for m1 — 10
// rounds of (64-seg reduce + one 128-elem rescan). 64KB smem -> 3 blocks/SM.
__global__ void __launch_bounds__(256)
topk_kernel(const float* __restrict__ gtb,
            const int*   __restrict__ n_gt,
            const float* __restrict__ scores) {
    extern __shared__ float smem[];
    float* sd0 = smem;            // [8192]
    float* sd1 = smem + NN;       // [8192]
    __shared__ float segv[2][64];
    __shared__ int   segi[2][64];

    const int mp = blockIdx.x, s = blockIdx.y, b = blockIdx.z;
    const int m0 = mp * 2, m1 = m0 + 1;
    const int ngt = n_gt[b];
    if (m0 >= ngt) return;                 // m1 checked later

    const int tid  = threadIdx.x;
    const int w    = tid >> 5;
    const int lane = tid & 31;

    const float g0x = gtb[(b*MM + m0)*7 + 0];
    const float g0y = gtb[(b*MM + m0)*7 + 1];
    const float g0z = gtb[(b*MM + m0)*7 + 2];
    const float g1x = gtb[(b*MM + m1)*7 + 0];
    const float g1y = gtb[(b*MM + m1)*7 + 1];
    const float g1z = gtb[(b*MM + m1)*7 + 2];

    const int gbase = (b*SS + s) * NN;

    // ---- phase 1: distances (float4) + fused 64x128-segment minima ----
    {
        const float4* px4 = (const float4*)(g_px + gbase);
        const float4* py4 = (const float4*)(g_py + gbase);
        const float4* pz4 = (const float4*)(g_pz + gbase);
        float4* sd04 = (float4*)sd0;
        float4* sd14 = (float4*)sd1;
        const int wq = w * 256;           // warp base in float4 units

        #pragma unroll
        for (int q = 0; q < 8; ++q) {     // one 128-elem segment per step
            const int e4 = wq + q*32 + lane;
            const float4 X = px4[e4];
            const float4 Y = py4[e4];
            const float4 Z = pz4[e4];
            const float xs[4] = {X.x, X.y, X.z, X.w};
            const float ys[4] = {Y.x, Y.y, Y.z, Y.w};
            const float zs[4] = {Z.x, Z.y, Z.z, Z.w};
            const int eb = e4 * 4;        // first element index of this quad
            float d0a[4], d1a[4];
            float rv0 = INF_F, rv1 = INF_F;
            int   ri0 = 0,     ri1 = 0;
            #pragma unroll
            for (int j = 0; j < 4; ++j) {
                float dx = xs[j] - g0x, dy = ys[j] - g0y, dz = zs[j] - g0z;
                d0a[j] = fmaf(dx, dx, fmaf(dy, dy, dz*dz));
                dx = xs[j] - g1x; dy = ys[j] - g1y; dz = zs[j] - g1z;
                d1a[j] = fmaf(dx, dx, fmaf(dy, dy, dz*dz));
                if (d0a[j] < rv0) { rv0 = d0a[j]; ri0 = eb + j; }  // strict <: lowest idx
                if (d1a[j] < rv1) { rv1 = d1a[j]; ri1 = eb + j; }
            }
            sd04[e4] = make_float4(d0a[0], d0a[1], d0a[2], d0a[3]);
            sd14[e4] = make_float4(d1a[0], d1a[1], d1a[2], d1a[3]);
            warp_min(rv0, ri0);
            warp_min(rv1, ri1);
            if (lane == 0) {
                const int sg = w*8 + q;
                segv[0][sg] = rv0; segi[0][sg] = ri0;
                segv[1][sg] = rv1; segi[1][sg] = ri1;
            }
        }
    }
    __syncthreads();

    // ---- phase 2: 10 selection rounds (warp 0 -> m0, warp 1 -> m1) ----
    if (w < 2) {
        if (w == 1 && m1 >= ngt) return;   // whole warp exits together
        float* sd  = (w == 0) ? sd0 : sd1;
        float* sgv = segv[w];
        int*   sgi = segi[w];

        float topv[10];
        int   topi[10];
        #pragma unroll
        for (int it = 0; it < 10; ++it) {
            float v  = sgv[lane];      int ei  = sgi[lane];
            float v2 = sgv[lane + 32]; int ei2 = sgi[lane + 32];
            if (v2 < v || (v2 == v && ei2 < ei)) { v = v2; ei = ei2; }
            warp_min(v, ei);
            v  = __shfl_sync(0xffffffffu, v,  0);
            ei = __shfl_sync(0xffffffffu, ei, 0);
            topv[it] = v; topi[it] = ei;
            const int sg = ei >> 7;
            if (lane == 0) sd[ei] = INF_F;
            __syncwarp();
            const int rb = sg*128 + lane*4;
            float nv = INF_F; int ni = rb;
            #pragma unroll
            for (int j = 0; j < 4; ++j) {
                const float t = sd[rb + j];
                if (t < nv) { nv = t; ni = rb + j; }
            }
            warp_min(nv, ni);
            if (lane == 0) { sgv[sg] = nv; sgi[sg] = ni; }
            __syncwarp();
        }

        if (lane == 0) {
            const int mm = (w == 0) ? m0 : m1;
            bool matched = false;
            #pragma unroll
            for (int j = 0; j < 10; ++j) {
                if (sqrtf(topv[j]) < 50.0f) {
                    atomicMax(&g_assign[gbase + topi[j]], mm);
                    matched = true;
                }
            }
            if (!matched) {
                float pg = 0.f;
                #pragma unroll
                for (int j = 0; j < 5; ++j)
                    pg += expf(-sqrtf(topv[j]) * 0.5f) * (1.0f - scores[gbase + topi[j]]);
                atomicAdd(&g_acc[4], (double)(pg * 0.2f));
                atomicOr(&g_flag[b*SS + s], 1u);
            }
        }
    }
}

// ---------------- fused reduction + final combine (last block) ----------------
__global__ void reduce_kernel(const float* __restrict__ scores,
                              const float* __restrict__ gtb,
                              float* __restrict__ out,
                              const float* __restrict__ wc,
                              const float* __restrict__ wo,
                              const float* __restrict__ wu) {
    const int gid = blockIdx.x * blockDim.x + threadIdx.x;
    const int stride = gridDim.x * blockDim.x;

    double c_sum = 0.0, sp1 = 0.0, sp2 = 0.0, np = 0.0;

    for (int i = gid; i < BSN; i += stride) {
        const int a = g_assign[i];
        const float x = scores[i];
        const float l1p = log1pf(expf(-fabsf(x)));   // shared tail of softplus(+-x)
        if (a >= 0) {
            np  += 1.0;
            sp1 += (double)(fmaxf(-x, 0.f) + l1p);    // softplus(-x)
            const int bb = i >> 15;                   // / (S*N)
            const float* g = gtb + (size_t)(bb*MM + a) * 7;
            float dd, ad;
            dd = g_px[i] - g[0]; ad = fabsf(dd);
            c_sum += (double)((ad < 1.f) ? 0.5f*ad*ad : ad - 0.5f);
            dd = g_py[i] - g[1]; ad = fabsf(dd);
            c_sum += (double)((ad < 1.f) ? 0.5f*ad*ad : ad - 0.5f);
            dd = g_pz[i] - g[2]; ad = fabsf(dd);
            c_sum += (double)((ad < 1.f) ? 0.5f*ad*ad : ad - 0.5f);
        } else {
            sp2 += (double)(fmaxf(x, 0.f) + l1p);     // softplus(x)
        }
    }

    #pragma unroll
    for (int off = 16; off; off >>= 1) {
        c_sum += __shfl_down_sync(0xffffffffu, c_sum, off);
        sp1   += __shfl_down_sync(0xffffffffu, sp1,   off);
        sp2   += __shfl_down_sync(0xffffffffu, sp2,   off);
        np    += __shfl_down_sync(0xffffffffu, np,    off);
    }
    __shared__ double sm[4][8];
    const int w = threadIdx.x >> 5;
    if ((threadIdx.x & 31) == 0) { sm[0][w]=c_sum; sm[1][w]=sp1; sm[2][w]=sp2; sm[3][w]=np; }
    __syncthreads();
    if (threadIdx.x == 0) {
        #pragma unroll
        for (int k = 1; k < 8; ++k) { c_sum+=sm[0][k]; sp1+=sm[1][k]; sp2+=sm[2][k]; np+=sm[3][k]; }
        atomicAdd(&g_acc[0], c_sum);
        atomicAdd(&g_acc[1], np);
        atomicAdd(&g_acc[2], sp1);
        atomicAdd(&g_acc[3], sp2);
        __threadfence();
        const unsigned t = atomicAdd(&g_done, 1u);
        if (t == gridDim.x - 1) {
            g_done = 0u;   // reset for next graph replay
            const double npos = g_acc[1];
            const double loss_center = g_acc[0] / fmax(npos * 3.0, 1.0);
            const double nneg = (double)BSN - npos;
            const double pw = fmin(10.0, nneg / fmax(npos, 1.0));
            const double loss_obj = (pw * g_acc[2] + g_acc[3]) / (double)BSN;
            int ne = 0;
            #pragma unroll
            for (int k = 0; k < BB*SS; ++k) ne += (g_flag[k] ? 1 : 0);
            const double loss_unm = g_acc[4] / fmax((double)ne, 1.0);
            out[0] = (float)(loss_center * (double)wc[0] +
                             loss_obj    * (double)wo[0] +
                             loss_unm    * (double)wu[0]);
        }
    }
}

// ---------------- launch ----------------
extern "C" void kernel_launch(void* const* d_in, const int* in_sizes, int n_in,
                              void* d_out, int out_size) {
    const float* pb     = (const float*)d_in[0];   // pred_boxes  [8,4,8192,7]
    const float* scores = (const float*)d_in[2];   // pred_scores [8,4,8192]
    const float* gtb    = (const float*)d_in[3];   // gt_boxes    [8,50,7]
    const int*   n_gt   = (const int*)d_in[5];     // [8]
    const float* wc     = (const float*)d_in[6];
    const float* wo     = (const float*)d_in[7];
    const float* wu     = (const float*)d_in[8];
    float* out = (float*)d_out;

    const int smem_bytes = 2 * NN * sizeof(float);   // 64 KB
    static bool attr_set = false;
    if (!attr_set) {
        cudaFuncSetAttribute(topk_kernel,
                             cudaFuncAttributeMaxDynamicSharedMemorySize,
                             smem_bytes);
        attr_set = true;
    }

    prep_kernel<<<512, 128>>>(pb);                  // 65536 threads, 4 boxes each
    dim3 grid(MM/2, SS, BB);                        // 25 x 4 x 8 = 800 blocks
    topk_kernel<<<grid, 256, smem_bytes>>>(gtb, n_gt, scores);
    reduce_kernel<<<148, 256>>>(scores, gtb, out, wc, wo, wu);
}

// round 11
// speedup vs baseline: 1.8427x; 1.2271x over previous
#include <cuda_runtime.h>
#include <math.h>

#define BB 8
#define SS 4
#define NN 8192
#define MM 50
#define BSN (BB*SS*NN)   // 262144
#define INF_F 3.4e38f

// ---------------- scratch (no allocations allowed) ----------------
__device__ float    g_px[BSN];
__device__ float    g_py[BSN];
__device__ float    g_pz[BSN];
__device__ int      g_assign[BSN];
__device__ unsigned g_flag[BB*SS];
// 0: center_sum, 1: n_pos, 2: sum_pos softplus(-x), 3: sum_neg softplus(x), 4: sum_unmatched
__device__ double   g_acc[5];
__device__ unsigned g_done;

// ---------------- prep: planarize coords (float4) + init scratch ----------------
__global__ void prep_kernel(const float* __restrict__ pb) {
    const int t = blockIdx.x * blockDim.x + threadIdx.x;   // 65536 threads
    const float4* q = (const float4*)pb;
    const size_t base = (size_t)t * 7;                     // float4 units
    const float4 q0 = q[base+0], q1 = q[base+1], q2 = q[base+2];
    const float4 q3 = q[base+3], q4 = q[base+4], q5 = q[base+5];
    float4 X = make_float4(q0.x, q1.w, q3.z, q5.y);        // F0,F7,F14,F21
    float4 Y = make_float4(q0.y, q2.x, q3.w, q5.z);        // F1,F8,F15,F22
    float4 Z = make_float4(q0.z, q2.y, q4.x, q5.w);        // F2,F9,F16,F23
    ((float4*)g_px)[t] = X;
    ((float4*)g_py)[t] = Y;
    ((float4*)g_pz)[t] = Z;
    ((int4*)g_assign)[t] = make_int4(-1, -1, -1, -1);
    if (t < BB*SS) g_flag[t] = 0u;
    if (t < 5)     g_acc[t]  = 0.0;
    if (t == 0)    g_done    = 0u;
}

// exact warp argmin via REDUX: v >= 0 always (sum of squares / FLT_MAX), so
// float bits are order-monotonic. Each lane's (v, idx) must already be the
// lowest-index minimum within that lane (strict-< scans guarantee this).
// Value-min first; lanes holding the min offer their index; index-min gives
// the global lowest index on ties -> matches jax.lax.top_k. Result in ALL lanes.
__device__ __forceinline__ void argmin32(float v, int idx, float& mv, int& mi) {
    const unsigned bits = __float_as_uint(v);
    const unsigned mn   = __reduce_min_sync(0xffffffffu, bits);
    const unsigned cand = (bits == mn) ? (unsigned)idx : 0xffffffffu;
    const unsigned im   = __reduce_min_sync(0xffffffffu, cand);
    mv = __uint_as_float(mn);
    mi = (int)im;
}

// ---------------- per-(b,s,gt-pair) top-10 selection ----------------
// One 256-thread block per (b, s, gt-pair). Geometry identical to the proven
// R9 kernel (64 segments x 128 elements; float4 loads/stores). Only the warp
// reductions changed: 5-deep shfl chains -> 2x REDUX argmin, and the phase-2
// rescan is one float4 per lane covering the FULL 128-elem segment
// (sg*32+lane over 32 lanes = 128 elements).
__global__ void __launch_bounds__(256)
topk_kernel(const float* __restrict__ gtb,
            const int*   __restrict__ n_gt,
            const float* __restrict__ scores) {
    extern __shared__ float smem[];
    float* sd0 = smem;            // [8192]
    float* sd1 = smem + NN;       // [8192]
    __shared__ float segv[2][64];
    __shared__ int   segi[2][64];

    const int mp = blockIdx.x, s = blockIdx.y, b = blockIdx.z;
    const int m0 = mp * 2, m1 = m0 + 1;
    const int ngt = n_gt[b];
    if (m0 >= ngt) return;                 // m1 checked later

    const int tid  = threadIdx.x;
    const int w    = tid >> 5;
    const int lane = tid & 31;

    const float g0x = gtb[(b*MM + m0)*7 + 0];
    const float g0y = gtb[(b*MM + m0)*7 + 1];
    const float g0z = gtb[(b*MM + m0)*7 + 2];
    const float g1x = gtb[(b*MM + m1)*7 + 0];
    const float g1y = gtb[(b*MM + m1)*7 + 1];
    const float g1z = gtb[(b*MM + m1)*7 + 2];

    const int gbase = (b*SS + s) * NN;

    // ---- phase 1: distances (float4) + fused 64x128-segment minima ----
    {
        const float4* px4 = (const float4*)(g_px + gbase);
        const float4* py4 = (const float4*)(g_py + gbase);
        const float4* pz4 = (const float4*)(g_pz + gbase);
        float4* sd04 = (float4*)sd0;
        float4* sd14 = (float4*)sd1;
        const int wq = w * 256;           // warp base in float4 units

        #pragma unroll
        for (int q = 0; q < 8; ++q) {     // one 128-elem segment per step
            const int e4 = wq + q*32 + lane;
            const float4 X = px4[e4];
            const float4 Y = py4[e4];
            const float4 Z = pz4[e4];
            const float xs[4] = {X.x, X.y, X.z, X.w};
            const float ys[4] = {Y.x, Y.y, Y.z, Y.w};
            const float zs[4] = {Z.x, Z.y, Z.z, Z.w};
            const int eb = e4 * 4;        // first element index of this quad
            float d0a[4], d1a[4];
            float rv0 = INF_F, rv1 = INF_F;
            int   ri0 = 0,     ri1 = 0;
            #pragma unroll
            for (int j = 0; j < 4; ++j) {
                float dx = xs[j] - g0x, dy = ys[j] - g0y, dz = zs[j] - g0z;
                d0a[j] = fmaf(dx, dx, fmaf(dy, dy, dz*dz));
                dx = xs[j] - g1x; dy = ys[j] - g1y; dz = zs[j] - g1z;
                d1a[j] = fmaf(dx, dx, fmaf(dy, dy, dz*dz));
                if (d0a[j] < rv0) { rv0 = d0a[j]; ri0 = eb + j; }  // strict <: lowest idx
                if (d1a[j] < rv1) { rv1 = d1a[j]; ri1 = eb + j; }
            }
            sd04[e4] = make_float4(d0a[0], d0a[1], d0a[2], d0a[3]);
            sd14[e4] = make_float4(d1a[0], d1a[1], d1a[2], d1a[3]);
            float mv0; int mi0;
            float mv1; int mi1;
            argmin32(rv0, ri0, mv0, mi0);
            argmin32(rv1, ri1, mv1, mi1);
            if (lane == 0) {
                const int sg = w*8 + q;
                segv[0][sg] = mv0; segi[0][sg] = mi0;
                segv[1][sg] = mv1; segi[1][sg] = mi1;
            }
        }
    }
    __syncthreads();

    // ---- phase 2: 10 selection rounds (warp 0 -> m0, warp 1 -> m1) ----
    if (w < 2) {
        if (w == 1 && m1 >= ngt) return;   // whole warp exits together
        float* sd  = (w == 0) ? sd0 : sd1;
        float* sgv = segv[w];
        int*   sgi = segi[w];

        float topv[10];
        int   topi[10];
        #pragma unroll
        for (int it = 0; it < 10; ++it) {
            // min over 64 segments (2 per lane; lex keeps lowest idx in-lane)
            float v  = sgv[lane];      int ei  = sgi[lane];
            float v2 = sgv[lane + 32]; int ei2 = sgi[lane + 32];
            if (v2 < v || (v2 == v && ei2 < ei)) { v = v2; ei = ei2; }
            float mv; int mi;
            argmin32(v, ei, mv, mi);      // result valid in ALL lanes
            topv[it] = mv; topi[it] = mi;
            const int sg = mi >> 7;
            if (lane == 0) sd[mi] = INF_F;
            __syncwarp();
            // rescan the FULL 128-elem segment: 32 lanes x one float4 each
            const float4 qv = ((const float4*)sd)[sg*32 + lane];
            const int rb = sg*128 + 4*lane;
            float nv = qv.x; int ni = rb;
            if (qv.y < nv) { nv = qv.y; ni = rb + 1; }
            if (qv.z < nv) { nv = qv.z; ni = rb + 2; }
            if (qv.w < nv) { nv = qv.w; ni = rb + 3; }
            float sm2; int sj;
            argmin32(nv, ni, sm2, sj);
            if (lane == 0) { sgv[sg] = sm2; sgi[sg] = sj; }
            __syncwarp();
        }

        if (lane == 0) {
            const int mm = (w == 0) ? m0 : m1;
            bool matched = false;
            #pragma unroll
            for (int j = 0; j < 10; ++j) {
                if (sqrtf(topv[j]) < 50.0f) {
                    atomicMax(&g_assign[gbase + topi[j]], mm);
                    matched = true;
                }
            }
            if (!matched) {
                float pg = 0.f;
                #pragma unroll
                for (int j = 0; j < 5; ++j)
                    pg += expf(-sqrtf(topv[j]) * 0.5f) * (1.0f - scores[gbase + topi[j]]);
                atomicAdd(&g_acc[4], (double)(pg * 0.2f));
                atomicOr(&g_flag[b*SS + s], 1u);
            }
        }
    }
}

// ---------------- fused reduction + final combine (last block) ----------------
__global__ void reduce_kernel(const float* __restrict__ scores,
                              const float* __restrict__ gtb,
                              float* __restrict__ out,
                              const float* __restrict__ wc,
                              const float* __restrict__ wo,
                              const float* __restrict__ wu) {
    const int gid = blockIdx.x * blockDim.x + threadIdx.x;
    const int stride = gridDim.x * blockDim.x;

    double c_sum = 0.0, sp1 = 0.0, sp2 = 0.0, np = 0.0;

    for (int i = gid; i < BSN; i += stride) {
        const int a = g_assign[i];
        const float x = scores[i];
        const float l1p = log1pf(expf(-fabsf(x)));   // shared tail of softplus(+-x)
        if (a >= 0) {
            np  += 1.0;
            sp1 += (double)(fmaxf(-x, 0.f) + l1p);    // softplus(-x)
            const int bb = i >> 15;                   // / (S*N)
            const float* g = gtb + (size_t)(bb*MM + a) * 7;
            float dd, ad;
            dd = g_px[i] - g[0]; ad = fabsf(dd);
            c_sum += (double)((ad < 1.f) ? 0.5f*ad*ad : ad - 0.5f);
            dd = g_py[i] - g[1]; ad = fabsf(dd);
            c_sum += (double)((ad < 1.f) ? 0.5f*ad*ad : ad - 0.5f);
            dd = g_pz[i] - g[2]; ad = fabsf(dd);
            c_sum += (double)((ad < 1.f) ? 0.5f*ad*ad : ad - 0.5f);
        } else {
            sp2 += (double)(fmaxf(x, 0.f) + l1p);     // softplus(x)
        }
    }

    #pragma unroll
    for (int off = 16; off; off >>= 1) {
        c_sum += __shfl_down_sync(0xffffffffu, c_sum, off);
        sp1   += __shfl_down_sync(0xffffffffu, sp1,   off);
        sp2   += __shfl_down_sync(0xffffffffu, sp2,   off);
        np    += __shfl_down_sync(0xffffffffu, np,    off);
    }
    __shared__ double sm[4][8];
    const int w = threadIdx.x >> 5;
    if ((threadIdx.x & 31) == 0) { sm[0][w]=c_sum; sm[1][w]=sp1; sm[2][w]=sp2; sm[3][w]=np; }
    __syncthreads();
    if (threadIdx.x == 0) {
        #pragma unroll
        for (int k = 1; k < 8; ++k) { c_sum+=sm[0][k]; sp1+=sm[1][k]; sp2+=sm[2][k]; np+=sm[3][k]; }
        atomicAdd(&g_acc[0], c_sum);
        atomicAdd(&g_acc[1], np);
        atomicAdd(&g_acc[2], sp1);
        atomicAdd(&g_acc[3], sp2);
        __threadfence();
        const unsigned t = atomicAdd(&g_done, 1u);
        if (t == gridDim.x - 1) {
            g_done = 0u;   // reset for next graph replay
            const double npos = g_acc[1];
            const double loss_center = g_acc[0] / fmax(npos * 3.0, 1.0);
            const double nneg = (double)BSN - npos;
            const double pw = fmin(10.0, nneg / fmax(npos, 1.0));
            const double loss_obj = (pw * g_acc[2] + g_acc[3]) / (double)BSN;
            int ne = 0;
            #pragma unroll
            for (int k = 0; k < BB*SS; ++k) ne += (g_flag[k] ? 1 : 0);
            const double loss_unm = g_acc[4] / fmax((double)ne, 1.0);
            out[0] = (float)(loss_center * (double)wc[0] +
                             loss_obj    * (double)wo[0] +
                             loss_unm    * (double)wu[0]);
        }
    }
}

// ---------------- launch ----------------
extern "C" void kernel_launch(void* const* d_in, const int* in_sizes, int n_in,
                              void* d_out, int out_size) {
    const float* pb     = (const float*)d_in[0];   // pred_boxes  [8,4,8192,7]
    const float* scores = (const float*)d_in[2];   // pred_scores [8,4,8192]
    const float* gtb    = (const float*)d_in[3];   // gt_boxes    [8,50,7]
    const int*   n_gt   = (const int*)d_in[5];     // [8]
    const float* wc     = (const float*)d_in[6];
    const float* wo     = (const float*)d_in[7];
    const float* wu     = (const float*)d_in[8];
    float* out = (float*)d_out;

    const int smem_bytes = 2 * NN * sizeof(float);   // 64 KB
    static bool attr_set = false;
    if (!attr_set) {
        cudaFuncSetAttribute(topk_kernel,
                             cudaFuncAttributeMaxDynamicSharedMemorySize,
                             smem_bytes);
        attr_set = true;
    }

    prep_kernel<<<512, 128>>>(pb);                  // 65536 threads, 4 boxes each
    dim3 grid(MM/2, SS, BB);                        // 25 x 4 x 8 = 800 blocks
    topk_kernel<<<grid, 256, smem_bytes>>>(gtb, n_gt, scores);
    reduce_kernel<<<148, 256>>>(scores, gtb, out, wc, wo, wu);
}